// round 4
// baseline (speedup 1.0000x reference)
#include <cuda_runtime.h>
#include <cuda_bf16.h>
#include <cstddef>
#include <cstdint>

// Problem constants (fixed shapes for this problem instance)
#define BB 32
#define TT 2048
#define DD 256
#define D4 (DD / 4)           // 64 float4 per row
#define CHUNK 32
#define NCHUNK (TT / CHUNK)   // 64

// Scratch: exclusive prefix sums csum[B, T+1, D]  (allocation-free: device global)
__device__ __align__(256) float g_csum[(size_t)BB * (TT + 1) * DD];
// Scratch: per-chunk partial sums part[B, NCHUNK, D] (becomes exclusive chunk prefix)
__device__ __align__(256) float g_part[(size_t)BB * NCHUNK * DD];

__device__ __forceinline__ float4 f4add(float4 a, float4 b) {
    return make_float4(a.x + b.x, a.y + b.y, a.z + b.z, a.w + b.w);
}

// ---- 256-bit L2-policy load/store helpers (sm_103a requires v8.b32 form) ----
__device__ __forceinline__ void st256_evict_last(float* p, float4 x, float4 y) {
    asm volatile(
        "st.global.L2::evict_last.v8.b32 [%0], {%1,%2,%3,%4,%5,%6,%7,%8};"
        :: "l"(p),
           "r"(__float_as_uint(x.x)), "r"(__float_as_uint(x.y)),
           "r"(__float_as_uint(x.z)), "r"(__float_as_uint(x.w)),
           "r"(__float_as_uint(y.x)), "r"(__float_as_uint(y.y)),
           "r"(__float_as_uint(y.z)), "r"(__float_as_uint(y.w))
        : "memory");
}
__device__ __forceinline__ void ld256_evict_last(const float* p, float4& x, float4& y) {
    uint32_t r0, r1, r2, r3, r4, r5, r6, r7;
    asm volatile(
        "ld.global.L2::evict_last.v8.b32 {%0,%1,%2,%3,%4,%5,%6,%7}, [%8];"
        : "=r"(r0), "=r"(r1), "=r"(r2), "=r"(r3),
          "=r"(r4), "=r"(r5), "=r"(r6), "=r"(r7)
        : "l"(p));
    x = make_float4(__uint_as_float(r0), __uint_as_float(r1),
                    __uint_as_float(r2), __uint_as_float(r3));
    y = make_float4(__uint_as_float(r4), __uint_as_float(r5),
                    __uint_as_float(r6), __uint_as_float(r7));
}
// output: streaming, evict-first — don't let 205MB of writes pollute L2
__device__ __forceinline__ void st_streaming(float* p, float4 v) {
    asm volatile("st.global.cs.v4.f32 [%0], {%1,%2,%3,%4};"
                 :: "l"(p), "f"(v.x), "f"(v.y), "f"(v.z), "f"(v.w) : "memory");
}

// ---------------------------------------------------------------------------
// K1: per-chunk partial sums. grid = (NCHUNK, B), block = 64 threads (one
// float4 column each). 32 independent float4 loads per thread -> high MLP.
// ---------------------------------------------------------------------------
__global__ void pe_partial(const float4* __restrict__ x) {
    const int l = threadIdx.x;          // 0..63 float4 lane
    const int c = blockIdx.x;
    const int b = blockIdx.y;
    const float4* p = x + ((size_t)b * TT + (size_t)c * CHUNK) * D4 + l;
    float4 s0 = make_float4(0.f, 0.f, 0.f, 0.f);
    float4 s1 = make_float4(0.f, 0.f, 0.f, 0.f);
#pragma unroll
    for (int i = 0; i < CHUNK; i += 2) {
        s0 = f4add(s0, __ldg(&p[(size_t)i * D4]));
        s1 = f4add(s1, __ldg(&p[(size_t)(i + 1) * D4]));
    }
    ((float4*)g_part)[((size_t)b * NCHUNK + c) * D4 + l] = f4add(s0, s1);
}

// ---------------------------------------------------------------------------
// K2: exclusive scan of chunk partials (in place). grid = B, block = 64.
// Tiny: 2 MB read + 2 MB write, all L2.
// ---------------------------------------------------------------------------
__global__ void pe_chunkscan() {
    const int l = threadIdx.x;
    const int b = blockIdx.x;
    float4* part = (float4*)g_part + (size_t)b * NCHUNK * D4 + l;
    float4 run = make_float4(0.f, 0.f, 0.f, 0.f);
#pragma unroll
    for (int k = 0; k < NCHUNK; k++) {
        float4 v = part[(size_t)k * D4];
        part[(size_t)k * D4] = run;
        run = f4add(run, v);
    }
}

// ---------------------------------------------------------------------------
// K3: write exclusive csum (pinned into L2 via 256-bit evict_last stores).
// grid = (NCHUNK, B), block = 32 threads; each lane owns 8 floats of D.
// ---------------------------------------------------------------------------
__global__ void pe_scan_write(const float* __restrict__ x) {
    const int l = threadIdx.x;          // 0..31, 8 floats each
    const int c = blockIdx.x;
    const int b = blockIdx.y;

    const float4* part = (const float4*)g_part +
                         ((size_t)b * NCHUNK + c) * D4 + 2 * l;
    float4 r0 = part[0];
    float4 r1 = part[1];

    const float4* p = (const float4*)(x + ((size_t)b * TT + (size_t)c * CHUNK) * DD) + 2 * l;
    float* q = g_csum + ((size_t)b * (TT + 1) + (size_t)c * CHUNK) * DD + 8 * l;

#pragma unroll
    for (int i = 0; i < CHUNK; i++) {
        st256_evict_last(q + (size_t)i * DD, r0, r1);
        float4 v0 = __ldg(&p[(size_t)i * D4]);
        float4 v1 = __ldg(&p[(size_t)i * D4 + 1]);
        r0 = f4add(r0, v0);
        r1 = f4add(r1, v1);
    }
    if (c == NCHUNK - 1) {
        st256_evict_last(q + (size_t)CHUNK * DD, r0, r1);   // csum[b, T, :]
    }
}

// ---------------------------------------------------------------------------
// K4: gather. One warp per (pair, half). 2P warp-tasks.
// out[p, half*D : half*D+D] = (csum[b, start+span] - csum[b, start]) / span
// csum reads: 256-bit L2 evict_last; output: streaming .cs stores.
// ---------------------------------------------------------------------------
__global__ void pe_gather(const int* __restrict__ p1_start,
                          const int* __restrict__ p1_span,
                          const int* __restrict__ p2_start,
                          const int* __restrict__ p2_span,
                          const int* __restrict__ pair_batch,
                          float* __restrict__ out,
                          int n_pairs) {
    const int warp_in_block = threadIdx.x >> 5;
    const int lane = threadIdx.x & 31;
    const int task = blockIdx.x * (blockDim.x >> 5) + warp_in_block;
    if (task >= 2 * n_pairs) return;

    const int p    = task >> 1;
    const int half = task & 1;

    const int start = half ? p2_start[p] : p1_start[p];
    const int span  = half ? p2_span[p]  : p1_span[p];
    const int b     = pair_batch[p];

    const float inv = 1.0f / (float)span;

    const float* cs = g_csum + (size_t)b * (TT + 1) * DD;
    const float* re = cs + (size_t)(start + span) * DD + 8 * lane;
    const float* rs = cs + (size_t)start * DD + 8 * lane;

    float4 e0, e1, s0, s1;
    ld256_evict_last(re, e0, e1);
    ld256_evict_last(rs, s0, s1);

    float4 o0, o1;
    o0.x = (e0.x - s0.x) * inv;  o0.y = (e0.y - s0.y) * inv;
    o0.z = (e0.z - s0.z) * inv;  o0.w = (e0.w - s0.w) * inv;
    o1.x = (e1.x - s1.x) * inv;  o1.y = (e1.y - s1.y) * inv;
    o1.z = (e1.z - s1.z) * inv;  o1.w = (e1.w - s1.w) * inv;

    float* o = out + (size_t)p * (2 * DD) + (size_t)half * DD + 8 * lane;
    st_streaming(o,     o0);
    st_streaming(o + 4, o1);
}

// ---------------------------------------------------------------------------
extern "C" void kernel_launch(void* const* d_in, const int* in_sizes, int n_in,
                              void* d_out, int out_size) {
    const float4* token_embs4 = (const float4*)d_in[0];
    const float*  token_embs  = (const float*)d_in[0];
    const int*    p1_start   = (const int*)d_in[1];
    const int*    p1_span    = (const int*)d_in[2];
    const int*    p2_start   = (const int*)d_in[3];
    const int*    p2_span    = (const int*)d_in[4];
    const int*    pair_batch = (const int*)d_in[5];
    float*        out        = (float*)d_out;

    const int P = in_sizes[1];

    dim3 gridCB(NCHUNK, BB);
    pe_partial<<<gridCB, 64>>>(token_embs4);
    pe_chunkscan<<<BB, 64>>>();
    pe_scan_write<<<gridCB, 32>>>(token_embs);

    const int warps_per_block = 8;                       // 256 threads
    const int tasks = 2 * P;
    const int blocks = (tasks + warps_per_block - 1) / warps_per_block;
    pe_gather<<<blocks, warps_per_block * 32>>>(p1_start, p1_span, p2_start,
                                                p2_span, pair_batch, out, P);
}